// round 13
// baseline (speedup 1.0000x reference)
#include <cuda_runtime.h>
#include <math.h>
#include <stdint.h>

#define B_   32
#define T_   256
#define D_   512
#define H_   8
#define DK_  64
#define TM_  1024
#define FF_  2048
#define NTOK (B_*T_)      // 8192
#define NMEM (B_*TM_)     // 32768

// ---------------- scratch (static device globals; no allocation allowed) ----
__device__ float g_x [NTOK*D_];
__device__ float g_n [NTOK*D_];
__device__ float g_q [NTOK*D_];
__device__ float g_k [NTOK*D_];
__device__ float g_v [NTOK*D_];
__device__ float g_a [NTOK*D_];
__device__ float g_f [NTOK*FF_];
__device__ float g_mk[NMEM*D_];
__device__ float g_mv[NMEM*D_];

// ---------------- small helpers ---------------------------------------------
__device__ __forceinline__ float tf32r(float x) {
    uint32_t u;
    asm("cvt.rna.tf32.f32 %0, %1;" : "=r"(u) : "f"(x));
    return __uint_as_float(u);
}
__device__ __forceinline__ uint32_t tf32u(float x) {
    uint32_t u;
    asm("cvt.rna.tf32.f32 %0, %1;" : "=r"(u) : "f"(x));
    return u;
}
__device__ __forceinline__ void mma_tf32(float* c, const uint32_t* a, const uint32_t* b) {
    asm volatile(
        "mma.sync.aligned.m16n8k8.row.col.f32.tf32.tf32.f32 "
        "{%0,%1,%2,%3}, {%4,%5,%6,%7}, {%8,%9}, {%0,%1,%2,%3};\n"
        : "+f"(c[0]), "+f"(c[1]), "+f"(c[2]), "+f"(c[3])
        : "r"(a[0]), "r"(a[1]), "r"(a[2]), "r"(a[3]), "r"(b[0]), "r"(b[1]));
}
__device__ __forceinline__ uint32_t sptr(const void* p) {
    return (uint32_t)__cvta_generic_to_shared(p);
}
__device__ __forceinline__ void cpa16(uint32_t dst, const void* src) {
    asm volatile("cp.async.cg.shared.global [%0], [%1], 16;\n"
                 :: "r"(dst), "l"(src) : "memory");
}

// ---------------- embedding + positional encoding ---------------------------
__global__ void embed_kernel(const int* __restrict__ target,
                             const float* __restrict__ emb,
                             float* __restrict__ x)
{
    int idx = blockIdx.x * blockDim.x + threadIdx.x;
    if (idx >= NTOK * D_) return;
    int n = idx / D_, d = idx - n * D_;
    int t = n % T_;
    int tok = target[n];
    float val = emb[(size_t)tok * D_ + d] * 22.62741699796952f;  // sqrt(512)
    int p2 = (d >> 1) << 1;
    float freq = expf((float)p2 * (-9.210340371976184f / 512.0f)); // -ln(10000)/D
    float ang = (float)t * freq;
    val += (d & 1) ? cosf(ang) : sinf(ang);
    x[idx] = val;
}

// ---------------- layernorm: one warp per 512-wide row ----------------------
__global__ void ln_kernel(const float* __restrict__ in, float* __restrict__ out,
                          const float* __restrict__ g, const float* __restrict__ b,
                          int nrows)
{
    int warp = threadIdx.x >> 5;
    int row  = blockIdx.x * 8 + warp;
    if (row >= nrows) return;
    int lane = threadIdx.x & 31;
    const float4* p = (const float4*)(in + (size_t)row * D_);
    float4 v[4];
    float sum = 0.f;
#pragma unroll
    for (int c = 0; c < 4; c++) {
        v[c] = p[lane + 32 * c];
        sum += v[c].x + v[c].y + v[c].z + v[c].w;
    }
#pragma unroll
    for (int o = 16; o > 0; o >>= 1) sum += __shfl_xor_sync(0xffffffffu, sum, o);
    float mu = sum * (1.0f / 512.0f);
    float vs = 0.f;
#pragma unroll
    for (int c = 0; c < 4; c++) {
        float dx = v[c].x - mu, dy = v[c].y - mu, dz = v[c].z - mu, dw = v[c].w - mu;
        vs += dx * dx + dy * dy + dz * dz + dw * dw;
    }
#pragma unroll
    for (int o = 16; o > 0; o >>= 1) vs += __shfl_xor_sync(0xffffffffu, vs, o);
    float rstd = rsqrtf(vs * (1.0f / 512.0f) + 1e-6f);
    float4* op = (float4*)(out + (size_t)row * D_);
    const float4* g4 = (const float4*)g;
    const float4* b4 = (const float4*)b;
#pragma unroll
    for (int c = 0; c < 4; c++) {
        float4 gg = g4[lane + 32 * c], bb = b4[lane + 32 * c], r;
        r.x = (v[c].x - mu) * rstd * gg.x + bb.x;
        r.y = (v[c].y - mu) * rstd * gg.y + bb.y;
        r.z = (v[c].z - mu) * rstd * gg.z + bb.z;
        r.w = (v[c].w - mu) * rstd * gg.w + bb.w;
        op[lane + 32 * c] = r;
    }
}

// ---------------- tf32 tensor-core GEMM, cp.async 3-stage pipeline ----------
// C[M,N] = A[M,K] @ W[K,N] + bias [+resid] [relu]
// CTA tile 128x128, KB=32, 256 threads (8 warps of 64x32).
// dyn smem: 3 stages of As[128][36] + Bs[32][136] = 107520 B, occ 2.
#define GEMM_SMEM (3*(128*36 + 32*136)*4)
__global__ __launch_bounds__(256, 2) void gemm_tc(
    const float* __restrict__ A, const float* __restrict__ W,
    const float* __restrict__ bias, const float* __restrict__ resid,
    float* __restrict__ C, int M, int K, int N, int relu)
{
    extern __shared__ float gsm[];
    const int STG = 128 * 36 + 32 * 136;
    float* Asm[3] = {gsm, gsm + STG, gsm + 2 * STG};
    float* Bsm[3] = {gsm + 128 * 36, gsm + STG + 128 * 36, gsm + 2 * STG + 128 * 36};
    int tid = threadIdx.x;
    int lane = tid & 31, warp = tid >> 5;
    int wm = (warp >> 2) * 64;
    int wn = (warp & 3) * 32;
    size_t m0 = (size_t)blockIdx.y * 128, n0 = (size_t)blockIdx.x * 128;

    float acc[4][4][4] = {};

    int arow = tid >> 1, acq = (tid & 1) * 16;
    int brow = tid >> 3, bcq = (tid & 7) * 4;
    int r = lane >> 2, cg = lane & 3;

    const float* Abase = A + (m0 + arow) * K + acq;
    const float* Wbase = W + (size_t)brow * N + n0 + bcq;

#define GLOAD(s, k0)                                                           \
    do {                                                                       \
        _Pragma("unroll")                                                      \
        for (int j = 0; j < 4; j++)                                            \
            cpa16(sptr(&Asm[s][arow * 36 + acq + 4 * j]), Abase + (k0) + 4 * j); \
        _Pragma("unroll")                                                      \
        for (int j = 0; j < 4; j++)                                            \
            cpa16(sptr(&Bsm[s][brow * 136 + bcq + 32 * j]), Wbase + (size_t)(k0) * N + 32 * j); \
        asm volatile("cp.async.commit_group;\n" ::: "memory");                 \
    } while (0)

    GLOAD(0, 0);
    GLOAD(1, 32);
    int nIt = K >> 5;
    int cur = 0;
    for (int i = 0; i < nIt; i++) {
        if (i + 2 < nIt) {
            int pre = cur + 2; if (pre >= 3) pre -= 3;
            GLOAD(pre, (i + 2) * 32);
            asm volatile("cp.async.wait_group 2;\n" ::: "memory");
        } else if (i + 1 < nIt) {
            asm volatile("cp.async.wait_group 1;\n" ::: "memory");
        } else {
            asm volatile("cp.async.wait_group 0;\n" ::: "memory");
        }
        __syncthreads();
        const float* as = Asm[cur];
        const float* bs = Bsm[cur];
#pragma unroll
        for (int ks = 0; ks < 4; ks++) {
            int kb = ks * 8;
            uint32_t af[4][4], bf[4][2];
#pragma unroll
            for (int mi = 0; mi < 4; mi++) {
                int rb = wm + mi * 16;
                af[mi][0] = tf32u(as[(rb + r) * 36 + kb + cg]);
                af[mi][1] = tf32u(as[(rb + 8 + r) * 36 + kb + cg]);
                af[mi][2] = tf32u(as[(rb + r) * 36 + kb + 4 + cg]);
                af[mi][3] = tf32u(as[(rb + 8 + r) * 36 + kb + 4 + cg]);
            }
#pragma unroll
            for (int ni = 0; ni < 4; ni++) {
                bf[ni][0] = tf32u(bs[(kb + cg) * 136 + wn + ni * 8 + r]);
                bf[ni][1] = tf32u(bs[(kb + 4 + cg) * 136 + wn + ni * 8 + r]);
            }
#pragma unroll
            for (int mi = 0; mi < 4; mi++)
#pragma unroll
                for (int ni = 0; ni < 4; ni++)
                    mma_tf32(acc[mi][ni], af[mi], bf[ni]);
        }
        __syncthreads();
        cur = (cur + 1 == 3) ? 0 : cur + 1;
    }

    int c2 = (lane & 3) * 2;
#pragma unroll
    for (int mi = 0; mi < 4; mi++) {
#pragma unroll
        for (int ni = 0; ni < 4; ni++) {
            size_t gm = m0 + wm + mi * 16 + r;
            size_t gn = n0 + wn + ni * 8 + c2;
            float b0v = bias[gn], b1v = bias[gn + 1];
            float v0 = acc[mi][ni][0] + b0v, v1 = acc[mi][ni][1] + b1v;
            float v2 = acc[mi][ni][2] + b0v, v3 = acc[mi][ni][3] + b1v;
            if (resid) {
                const float2 r0 = *(const float2*)(resid + gm * N + gn);
                const float2 r1 = *(const float2*)(resid + (gm + 8) * N + gn);
                v0 += r0.x; v1 += r0.y; v2 += r1.x; v3 += r1.y;
            }
            if (relu) {
                v0 = fmaxf(v0, 0.f); v1 = fmaxf(v1, 0.f);
                v2 = fmaxf(v2, 0.f); v3 = fmaxf(v3, 0.f);
            }
            *(float2*)(C + gm * N + gn) = make_float2(v0, v1);
            *(float2*)(C + (gm + 8) * N + gn) = make_float2(v2, v3);
        }
    }
}

// ---------------- tf32 tensor-core flash attention, cp.async K/V pipeline ----
// CTA: 128 q-rows of one (b,h); 256 threads = 8 warps x 16 rows.
// K/V chunks double-buffered via cp.async; tf32 conversion at fragment read
// (mathematically identical to converting at store).
// Vb: 64x64 chunk in 8x8-block k-major layout -> 64 blocks, stride 72.
// Pad-row semantics preserved: no chunk skipping; masked = -1e9 before exp.
#define FLASH_SMEM ((128*68 + 2*(64*68 + 64*72) + 128*68) * 4)   // 141312 B
__global__ __launch_bounds__(256, 1) void flash_tc(
    const float* __restrict__ Q, const float* __restrict__ Kg,
    const float* __restrict__ Vg, float* __restrict__ O, int Tk,
    const int* __restrict__ target, int causal)
{
    extern __shared__ float fsm[];
    float* Qs = fsm;                                   // [128][68]
    float* Kst[2]; float* Vbt[2];
    Kst[0] = fsm + 128 * 68;
    Vbt[0] = Kst[0] + 64 * 68;
    Kst[1] = Vbt[0] + 64 * 72;
    Vbt[1] = Kst[1] + 64 * 68;
    float* Ps = Vbt[1] + 64 * 72;                      // [128][68]

    int tid = threadIdx.x, lane = tid & 31, warp = tid >> 5;
    int z = blockIdx.y, b = z >> 3, h = z & 7;
    int tq0 = blockIdx.x * 128;
    int r = lane >> 2, c = lane & 3;
    int w16 = warp * 16;

    // K/V chunk prefetch (raw fp32; tf32 at fragment read)
    // V: element (tk,d) -> Vb[((tk>>3)*8+(d>>3))*72 + (tk&7)*8 + (d&7)];
    //    16B-chunk of 4 d's stays contiguous inside one 8-float inner row.
#define FKV(s, kt0)                                                            \
    do {                                                                       \
        int rowk = tid >> 4, c4 = (tid & 15) * 4;                              \
        _Pragma("unroll")                                                      \
        for (int it = 0; it < 4; it++, rowk += 16)                             \
            cpa16(sptr(&Kst[s][rowk * 68 + c4]),                               \
                  Kg + (size_t)(b * Tk + (kt0) + rowk) * D_ + h * DK_ + c4);   \
        int tkv = tid >> 4;                                                    \
        int bd = (tid & 15) >> 1;                                              \
        int id = (tid & 1) * 4;                                                \
        _Pragma("unroll")                                                      \
        for (int it = 0; it < 4; it++, tkv += 16)                              \
            cpa16(sptr(&Vbt[s][((tkv >> 3) * 8 + bd) * 72 + (tkv & 7) * 8 + id]), \
                  Vg + (size_t)(b * Tk + (kt0) + tkv) * D_ + h * DK_ + (tid & 15) * 4); \
        asm volatile("cp.async.commit_group;\n" ::: "memory");                 \
    } while (0)

    FKV(0, 0);   // prefetch chunk 0

    // load Q tile 128x64 (tf32-converted)
    {
        int row = tid >> 4, c4 = (tid & 15) * 4;
#pragma unroll
        for (int it = 0; it < 8; it++, row += 16) {
            float4 q4 = *(const float4*)(Q + (size_t)(b * T_ + tq0 + row) * D_ + h * DK_ + c4);
            q4.x = tf32r(q4.x); q4.y = tf32r(q4.y); q4.z = tf32r(q4.z); q4.w = tf32r(q4.w);
            *(float4*)&Qs[row * 68 + c4] = q4;
        }
    }

    int row0g = tq0 + w16 + r;
    int row1g = row0g + 8;
    bool rowok0 = causal ? (target[b * T_ + row0g] != 0) : true;
    bool rowok1 = causal ? (target[b * T_ + row1g] != 0) : true;

    float m0 = -1e30f, m1 = -1e30f, l0 = 0.f, l1 = 0.f;
    float o[8][4] = {};

    int nch = Tk >> 6;
    for (int ic = 0; ic < nch; ic++) {
        int s = ic & 1;
        if (ic + 1 < nch) {
            FKV(s ^ 1, (ic + 1) * 64);
            asm volatile("cp.async.wait_group 1;\n" ::: "memory");
        } else {
            asm volatile("cp.async.wait_group 0;\n" ::: "memory");
        }
        __syncthreads();   // stage s (and Qs on ic==0) visible to all warps
        const float* Ks = Kst[s];
        const float* Vb = Vbt[s];
        int kt0 = ic * 64;

        // S = Q K^T for this warp's 16 rows x 64 cols
        float sc[8][4] = {};
#pragma unroll
        for (int kb = 0; kb < 64; kb += 8) {
            uint32_t aa[4];
            aa[0] = __float_as_uint(Qs[(w16 + r) * 68 + kb + c]);
            aa[1] = __float_as_uint(Qs[(w16 + 8 + r) * 68 + kb + c]);
            aa[2] = __float_as_uint(Qs[(w16 + r) * 68 + kb + 4 + c]);
            aa[3] = __float_as_uint(Qs[(w16 + 8 + r) * 68 + kb + 4 + c]);
#pragma unroll
            for (int nt = 0; nt < 8; nt++) {
                uint32_t bb[2];
                bb[0] = tf32u(Ks[(nt * 8 + r) * 68 + kb + c]);
                bb[1] = tf32u(Ks[(nt * 8 + r) * 68 + kb + 4 + c]);
                mma_tf32(sc[nt], aa, bb);
            }
        }

        // scale + mask + online softmax (rows row0g, row1g)
        float mx0 = -1e30f, mx1 = -1e30f;
#pragma unroll
        for (int nt = 0; nt < 8; nt++) {
            int col0 = kt0 + nt * 8 + 2 * c;
            int col1 = col0 + 1;
            bool ok00 = !causal || (rowok0 && col0 <= row0g);
            bool ok01 = !causal || (rowok0 && col1 <= row0g);
            bool ok10 = !causal || (rowok1 && col0 <= row1g);
            bool ok11 = !causal || (rowok1 && col1 <= row1g);
            sc[nt][0] = ok00 ? sc[nt][0] * 0.125f : -1e9f;
            sc[nt][1] = ok01 ? sc[nt][1] * 0.125f : -1e9f;
            sc[nt][2] = ok10 ? sc[nt][2] * 0.125f : -1e9f;
            sc[nt][3] = ok11 ? sc[nt][3] * 0.125f : -1e9f;
            mx0 = fmaxf(mx0, fmaxf(sc[nt][0], sc[nt][1]));
            mx1 = fmaxf(mx1, fmaxf(sc[nt][2], sc[nt][3]));
        }
        mx0 = fmaxf(mx0, __shfl_xor_sync(0xffffffffu, mx0, 1));
        mx0 = fmaxf(mx0, __shfl_xor_sync(0xffffffffu, mx0, 2));
        mx1 = fmaxf(mx1, __shfl_xor_sync(0xffffffffu, mx1, 1));
        mx1 = fmaxf(mx1, __shfl_xor_sync(0xffffffffu, mx1, 2));
        float mn0 = fmaxf(m0, mx0), mn1 = fmaxf(m1, mx1);
        float al0 = expf(m0 - mn0), al1 = expf(m1 - mn1);
        m0 = mn0; m1 = mn1;
        float rs0 = 0.f, rs1 = 0.f;
#pragma unroll
        for (int nt = 0; nt < 8; nt++) {
            sc[nt][0] = expf(sc[nt][0] - mn0);
            sc[nt][1] = expf(sc[nt][1] - mn0);
            sc[nt][2] = expf(sc[nt][2] - mn1);
            sc[nt][3] = expf(sc[nt][3] - mn1);
            rs0 += sc[nt][0] + sc[nt][1];
            rs1 += sc[nt][2] + sc[nt][3];
        }
        rs0 += __shfl_xor_sync(0xffffffffu, rs0, 1);
        rs0 += __shfl_xor_sync(0xffffffffu, rs0, 2);
        rs1 += __shfl_xor_sync(0xffffffffu, rs1, 1);
        rs1 += __shfl_xor_sync(0xffffffffu, rs1, 2);
        l0 = l0 * al0 + rs0;
        l1 = l1 * al1 + rs1;
#pragma unroll
        for (int nt = 0; nt < 8; nt++) {
            o[nt][0] *= al0; o[nt][1] *= al0;
            o[nt][2] *= al1; o[nt][3] *= al1;
        }

        // stage P in smem (warp-private rows), tf32-converted
#pragma unroll
        for (int nt = 0; nt < 8; nt++) {
            *(float2*)&Ps[(w16 + r) * 68 + nt * 8 + 2 * c] =
                make_float2(tf32r(sc[nt][0]), tf32r(sc[nt][1]));
            *(float2*)&Ps[(w16 + 8 + r) * 68 + nt * 8 + 2 * c] =
                make_float2(tf32r(sc[nt][2]), tf32r(sc[nt][3]));
        }
        __syncwarp();

        // O += P V
#pragma unroll
        for (int kb = 0; kb < 64; kb += 8) {
            uint32_t aa[4];
            aa[0] = __float_as_uint(Ps[(w16 + r) * 68 + kb + c]);
            aa[1] = __float_as_uint(Ps[(w16 + 8 + r) * 68 + kb + c]);
            aa[2] = __float_as_uint(Ps[(w16 + r) * 68 + kb + 4 + c]);
            aa[3] = __float_as_uint(Ps[(w16 + 8 + r) * 68 + kb + 4 + c]);
            int kbi = kb >> 3;
#pragma unroll
            for (int nt = 0; nt < 8; nt++) {
                uint32_t bb[2];
                bb[0] = tf32u(Vb[(kbi * 8 + nt) * 72 + c * 8 + r]);
                bb[1] = tf32u(Vb[(kbi * 8 + nt) * 72 + 32 + c * 8 + r]);
                mma_tf32(o[nt], aa, bb);
            }
        }
        __syncthreads();   // all warps done reading stage s before its reuse
    }

    float inv0 = 1.0f / l0, inv1 = 1.0f / l1;
#pragma unroll
    for (int nt = 0; nt < 8; nt++) {
        size_t g0 = (size_t)(b * T_ + row0g) * D_ + h * DK_ + nt * 8 + 2 * c;
        *(float2*)(O + g0)          = make_float2(o[nt][0] * inv0, o[nt][1] * inv0);
        *(float2*)(O + g0 + 8 * D_) = make_float2(o[nt][2] * inv1, o[nt][3] * inv1);
    }
}

// ---------------- host orchestration ----------------------------------------
extern "C" void kernel_launch(void* const* d_in, const int* in_sizes, int n_in,
                              void* d_out, int out_size)
{
    (void)in_sizes; (void)n_in; (void)out_size;
    float *x, *nb, *q, *k, *v, *a, *f, *mk, *mv;
    cudaGetSymbolAddress((void**)&x,  g_x);
    cudaGetSymbolAddress((void**)&nb, g_n);
    cudaGetSymbolAddress((void**)&q,  g_q);
    cudaGetSymbolAddress((void**)&k,  g_k);
    cudaGetSymbolAddress((void**)&v,  g_v);
    cudaGetSymbolAddress((void**)&a,  g_a);
    cudaGetSymbolAddress((void**)&f,  g_f);
    cudaGetSymbolAddress((void**)&mk, g_mk);
    cudaGetSymbolAddress((void**)&mv, g_mv);

    static int attr_set = 0;
    if (!attr_set) {
        cudaFuncSetAttribute(gemm_tc,  cudaFuncAttributeMaxDynamicSharedMemorySize, GEMM_SMEM);
        cudaFuncSetAttribute(flash_tc, cudaFuncAttributeMaxDynamicSharedMemorySize, FLASH_SMEM);
        attr_set = 1;
    }

    // setup_inputs() dict order (verified R2: rel_err 1.2e-6)
    const int*   target = (const int*)  d_in[0];
    const float* memory = (const float*)d_in[1];
    const float* emb    = (const float*)d_in[2];
    const float* ln_g   = (const float*)d_in[3];
    const float* ln_b   = (const float*)d_in[4];
    const float* ff_w1  = (const float*)d_in[5];
    const float* ff_b1  = (const float*)d_in[6];
    const float* ff_w2  = (const float*)d_in[7];
    const float* ff_b2  = (const float*)d_in[8];
    const float* sa_wq  = (const float*)d_in[9];
    const float* sa_bq  = (const float*)d_in[10];
    const float* ca_wq  = (const float*)d_in[11];
    const float* ca_bq  = (const float*)d_in[12];
    const float* sa_wk  = (const float*)d_in[13];
    const float* sa_bk  = (const float*)d_in[14];
    const float* ca_wk  = (const float*)d_in[15];
    const float* ca_bk  = (const float*)d_in[16];
    const float* sa_wv  = (const float*)d_in[17];
    const float* sa_bv  = (const float*)d_in[18];
    const float* ca_wv  = (const float*)d_in[19];
    const float* ca_bv  = (const float*)d_in[20];
    const float* sa_wo  = (const float*)d_in[21];
    const float* sa_bo  = (const float*)d_in[22];
    const float* ca_wo  = (const float*)d_in[23];
    const float* ca_bo  = (const float*)d_in[24];

    embed_kernel<<<(NTOK * D_ + 255) / 256, 256>>>(target, emb, x);

    // cross-attn K/V of memory: computed ONCE (shared weights, static memory)
    gemm_tc<<<dim3(D_ / 128, NMEM / 128), 256, GEMM_SMEM>>>(memory, ca_wk, ca_bk, nullptr, mk, NMEM, D_, D_, 0);
    gemm_tc<<<dim3(D_ / 128, NMEM / 128), 256, GEMM_SMEM>>>(memory, ca_wv, ca_bv, nullptr, mv, NMEM, D_, D_, 0);

    dim3 gProj(D_ / 128, NTOK / 128);   // (4,64)
    dim3 gFF1 (FF_ / 128, NTOK / 128);  // (16,64)
    dim3 gFlash(T_ / 128, B_ * H_);     // (2,256)

    for (int stk = 0; stk < 3; stk++) {
        // ---- self attention ----
        ln_kernel<<<NTOK / 8, 256>>>(x, nb, ln_g, ln_b, NTOK);
        gemm_tc<<<gProj, 256, GEMM_SMEM>>>(nb, sa_wq, sa_bq, nullptr, q, NTOK, D_, D_, 0);
        gemm_tc<<<gProj, 256, GEMM_SMEM>>>(nb, sa_wk, sa_bk, nullptr, k, NTOK, D_, D_, 0);
        gemm_tc<<<gProj, 256, GEMM_SMEM>>>(nb, sa_wv, sa_bv, nullptr, v, NTOK, D_, D_, 0);
        flash_tc<<<gFlash, 256, FLASH_SMEM>>>(q, k, v, a, T_, target, 1);
        gemm_tc<<<gProj, 256, GEMM_SMEM>>>(a, sa_wo, sa_bo, x, x, NTOK, D_, D_, 0);

        // ---- cross attention ----
        ln_kernel<<<NTOK / 8, 256>>>(x, nb, ln_g, ln_b, NTOK);
        gemm_tc<<<gProj, 256, GEMM_SMEM>>>(nb, ca_wq, ca_bq, nullptr, q, NTOK, D_, D_, 0);
        flash_tc<<<gFlash, 256, FLASH_SMEM>>>(q, mk, mv, a, TM_, nullptr, 0);
        gemm_tc<<<gProj, 256, GEMM_SMEM>>>(a, ca_wo, ca_bo, x, x, NTOK, D_, D_, 0);

        // ---- feed forward ----
        ln_kernel<<<NTOK / 8, 256>>>(x, nb, ln_g, ln_b, NTOK);
        gemm_tc<<<gFF1, 256, GEMM_SMEM>>>(nb, ff_w1, ff_b1, nullptr, f, NTOK, D_, FF_, 1);
        gemm_tc<<<gProj, 256, GEMM_SMEM>>>(f, ff_w2, ff_b2, x, x, NTOK, FF_, D_, 0);
    }

    ln_kernel<<<NTOK / 8, 256>>>(x, (float*)d_out, ln_g, ln_b, NTOK);
}

// round 15
// speedup vs baseline: 1.0948x; 1.0948x over previous
#include <cuda_runtime.h>
#include <math.h>
#include <stdint.h>

#define B_   32
#define T_   256
#define D_   512
#define H_   8
#define DK_  64
#define TM_  1024
#define FF_  2048
#define NTOK (B_*T_)      // 8192
#define NMEM (B_*TM_)     // 32768

// ---------------- scratch (static device globals; no allocation allowed) ----
__device__ float g_x [NTOK*D_];
__device__ float g_n [NTOK*D_];
__device__ float g_q [NTOK*D_];
__device__ float g_k [NTOK*D_];
__device__ float g_v [NTOK*D_];
__device__ float g_a [NTOK*D_];
__device__ float g_f [NTOK*FF_];
__device__ float g_mk[NMEM*D_];
__device__ float g_mv[NMEM*D_];

// ---------------- small helpers ---------------------------------------------
__device__ __forceinline__ float tf32r(float x) {
    uint32_t u;
    asm("cvt.rna.tf32.f32 %0, %1;" : "=r"(u) : "f"(x));
    return __uint_as_float(u);
}
__device__ __forceinline__ uint32_t tf32u(float x) {
    uint32_t u;
    asm("cvt.rna.tf32.f32 %0, %1;" : "=r"(u) : "f"(x));
    return u;
}
__device__ __forceinline__ void mma_tf32(float* c, const uint32_t* a, const uint32_t* b) {
    asm volatile(
        "mma.sync.aligned.m16n8k8.row.col.f32.tf32.tf32.f32 "
        "{%0,%1,%2,%3}, {%4,%5,%6,%7}, {%8,%9}, {%0,%1,%2,%3};\n"
        : "+f"(c[0]), "+f"(c[1]), "+f"(c[2]), "+f"(c[3])
        : "r"(a[0]), "r"(a[1]), "r"(a[2]), "r"(a[3]), "r"(b[0]), "r"(b[1]));
}
__device__ __forceinline__ uint32_t sptr(const void* p) {
    return (uint32_t)__cvta_generic_to_shared(p);
}
__device__ __forceinline__ void cpa16(uint32_t dst, const void* src) {
    asm volatile("cp.async.cg.shared.global [%0], [%1], 16;\n"
                 :: "r"(dst), "l"(src) : "memory");
}

// ---------------- embedding + positional encoding ---------------------------
__global__ void embed_kernel(const int* __restrict__ target,
                             const float* __restrict__ emb,
                             float* __restrict__ x)
{
    int idx = blockIdx.x * blockDim.x + threadIdx.x;
    if (idx >= NTOK * D_) return;
    int n = idx / D_, d = idx - n * D_;
    int t = n % T_;
    int tok = target[n];
    float val = emb[(size_t)tok * D_ + d] * 22.62741699796952f;  // sqrt(512)
    int p2 = (d >> 1) << 1;
    float freq = expf((float)p2 * (-9.210340371976184f / 512.0f)); // -ln(10000)/D
    float ang = (float)t * freq;
    val += (d & 1) ? cosf(ang) : sinf(ang);
    x[idx] = val;
}

// ---------------- layernorm: one warp per 512-wide row ----------------------
__global__ void ln_kernel(const float* __restrict__ in, float* __restrict__ out,
                          const float* __restrict__ g, const float* __restrict__ b,
                          int nrows)
{
    int warp = threadIdx.x >> 5;
    int row  = blockIdx.x * 8 + warp;
    if (row >= nrows) return;
    int lane = threadIdx.x & 31;
    const float4* p = (const float4*)(in + (size_t)row * D_);
    float4 v[4];
    float sum = 0.f;
#pragma unroll
    for (int c = 0; c < 4; c++) {
        v[c] = p[lane + 32 * c];
        sum += v[c].x + v[c].y + v[c].z + v[c].w;
    }
#pragma unroll
    for (int o = 16; o > 0; o >>= 1) sum += __shfl_xor_sync(0xffffffffu, sum, o);
    float mu = sum * (1.0f / 512.0f);
    float vs = 0.f;
#pragma unroll
    for (int c = 0; c < 4; c++) {
        float dx = v[c].x - mu, dy = v[c].y - mu, dz = v[c].z - mu, dw = v[c].w - mu;
        vs += dx * dx + dy * dy + dz * dz + dw * dw;
    }
#pragma unroll
    for (int o = 16; o > 0; o >>= 1) vs += __shfl_xor_sync(0xffffffffu, vs, o);
    float rstd = rsqrtf(vs * (1.0f / 512.0f) + 1e-6f);
    float4* op = (float4*)(out + (size_t)row * D_);
    const float4* g4 = (const float4*)g;
    const float4* b4 = (const float4*)b;
#pragma unroll
    for (int c = 0; c < 4; c++) {
        float4 gg = g4[lane + 32 * c], bb = b4[lane + 32 * c], r;
        r.x = (v[c].x - mu) * rstd * gg.x + bb.x;
        r.y = (v[c].y - mu) * rstd * gg.y + bb.y;
        r.z = (v[c].z - mu) * rstd * gg.z + bb.z;
        r.w = (v[c].w - mu) * rstd * gg.w + bb.w;
        op[lane + 32 * c] = r;
    }
}

// ---------------- tf32 tensor-core GEMM, cp.async double-buffered -----------
// (exact R12 winner — untouched)
#define GEMM_SMEM (2*(128*36 + 32*136)*4)
__global__ __launch_bounds__(256, 2) void gemm_tc(
    const float* __restrict__ A, const float* __restrict__ W,
    const float* __restrict__ bias, const float* __restrict__ resid,
    float* __restrict__ C, int M, int K, int N, int relu)
{
    extern __shared__ float gsm[];
    float* Asm[2] = {gsm, gsm + 128 * 36};
    float* Bsm[2] = {gsm + 2 * 128 * 36, gsm + 2 * 128 * 36 + 32 * 136};
    int tid = threadIdx.x;
    int lane = tid & 31, warp = tid >> 5;
    int wm = (warp >> 2) * 64;
    int wn = (warp & 3) * 32;
    size_t m0 = (size_t)blockIdx.y * 128, n0 = (size_t)blockIdx.x * 128;

    float acc[4][4][4] = {};

    int arow = tid >> 1, acq = (tid & 1) * 16;
    int brow = tid >> 3, bcq = (tid & 7) * 4;
    int r = lane >> 2, cg = lane & 3;

    const float* Abase = A + (m0 + arow) * K + acq;
    const float* Wbase = W + (size_t)brow * N + n0 + bcq;

#define GLOAD(s, k0)                                                           \
    do {                                                                       \
        _Pragma("unroll")                                                      \
        for (int j = 0; j < 4; j++)                                            \
            cpa16(sptr(&Asm[s][arow * 36 + acq + 4 * j]), Abase + (k0) + 4 * j); \
        _Pragma("unroll")                                                      \
        for (int j = 0; j < 4; j++)                                            \
            cpa16(sptr(&Bsm[s][brow * 136 + bcq + 32 * j]), Wbase + (size_t)(k0) * N + 32 * j); \
        asm volatile("cp.async.commit_group;\n" ::: "memory");                 \
    } while (0)

    GLOAD(0, 0);
    int st = 0;
    for (int k0 = 0; k0 < K; k0 += 32) {
        if (k0 + 32 < K) { GLOAD(st ^ 1, k0 + 32); asm volatile("cp.async.wait_group 1;\n" ::: "memory"); }
        else             { asm volatile("cp.async.wait_group 0;\n" ::: "memory"); }
        __syncthreads();
        const float* as = Asm[st];
        const float* bs = Bsm[st];
#pragma unroll
        for (int ks = 0; ks < 4; ks++) {
            int kb = ks * 8;
            uint32_t af[4][4], bf[4][2];
#pragma unroll
            for (int mi = 0; mi < 4; mi++) {
                int rb = wm + mi * 16;
                af[mi][0] = tf32u(as[(rb + r) * 36 + kb + cg]);
                af[mi][1] = tf32u(as[(rb + 8 + r) * 36 + kb + cg]);
                af[mi][2] = tf32u(as[(rb + r) * 36 + kb + 4 + cg]);
                af[mi][3] = tf32u(as[(rb + 8 + r) * 36 + kb + 4 + cg]);
            }
#pragma unroll
            for (int ni = 0; ni < 4; ni++) {
                bf[ni][0] = tf32u(bs[(kb + cg) * 136 + wn + ni * 8 + r]);
                bf[ni][1] = tf32u(bs[(kb + 4 + cg) * 136 + wn + ni * 8 + r]);
            }
#pragma unroll
            for (int mi = 0; mi < 4; mi++)
#pragma unroll
                for (int ni = 0; ni < 4; ni++)
                    mma_tf32(acc[mi][ni], af[mi], bf[ni]);
        }
        __syncthreads();
        st ^= 1;
    }

    int c2 = (lane & 3) * 2;
#pragma unroll
    for (int mi = 0; mi < 4; mi++) {
#pragma unroll
        for (int ni = 0; ni < 4; ni++) {
            size_t gm = m0 + wm + mi * 16 + r;
            size_t gn = n0 + wn + ni * 8 + c2;
            float b0v = bias[gn], b1v = bias[gn + 1];
            float v0 = acc[mi][ni][0] + b0v, v1 = acc[mi][ni][1] + b1v;
            float v2 = acc[mi][ni][2] + b0v, v3 = acc[mi][ni][3] + b1v;
            if (resid) {
                const float2 r0 = *(const float2*)(resid + gm * N + gn);
                const float2 r1 = *(const float2*)(resid + (gm + 8) * N + gn);
                v0 += r0.x; v1 += r0.y; v2 += r1.x; v3 += r1.y;
            }
            if (relu) {
                v0 = fmaxf(v0, 0.f); v1 = fmaxf(v1, 0.f);
                v2 = fmaxf(v2, 0.f); v3 = fmaxf(v3, 0.f);
            }
            *(float2*)(C + gm * N + gn) = make_float2(v0, v1);
            *(float2*)(C + (gm + 8) * N + gn) = make_float2(v2, v3);
        }
    }
}

// ---------------- tf32 flash attention: 32-chunk cp.async, occupancy 2 -------
// CTA: 128 q-rows of one (b,h); 256 threads = 8 warps x 16 rows.
// K/V in 32-row chunks, double-buffered (2 stages == footprint of one 64-chunk):
// smem = Qs 128x68 + 2*(K 32x68 + V 32 blk x72) + Ps 128x36 = 89088 B -> occ 2.
// tf32 conversion at fragment read. Pad-row semantics: no chunk skipping.
#define FLASH_SMEM ((128*68 + 2*(32*68 + 32*72) + 128*36) * 4)   // 89088 B
__global__ __launch_bounds__(256, 2) void flash_tc(
    const float* __restrict__ Q, const float* __restrict__ Kg,
    const float* __restrict__ Vg, float* __restrict__ O, int Tk,
    const int* __restrict__ target, int causal)
{
    extern __shared__ float fsm[];
    float* Qs = fsm;                          // [128][68]
    float* Kst[2]; float* Vbt[2];
    Kst[0] = fsm + 128 * 68;
    Vbt[0] = Kst[0] + 32 * 68;
    Kst[1] = Vbt[0] + 32 * 72;
    Vbt[1] = Kst[1] + 32 * 68;
    float* Ps = Vbt[1] + 32 * 72;             // [128][36]

    int tid = threadIdx.x, lane = tid & 31, warp = tid >> 5;
    int z = blockIdx.y, b = z >> 3, h = z & 7;
    int tq0 = blockIdx.x * 128;
    int r = lane >> 2, c = lane & 3;
    int w16 = warp * 16;

    // prefetch one 32-row K/V chunk into stage s.
    // V element (tk,d) -> Vb[((tk>>3)*8 + (d>>3))*72 + (tk&7)*8 + (d&7)]
#define FKV(s, kt0)                                                            \
    do {                                                                       \
        int rowk = tid >> 4, c4 = (tid & 15) * 4;                              \
        cpa16(sptr(&Kst[s][rowk * 68 + c4]),                                   \
              Kg + (size_t)(b * Tk + (kt0) + rowk) * D_ + h * DK_ + c4);       \
        cpa16(sptr(&Kst[s][(rowk + 16) * 68 + c4]),                            \
              Kg + (size_t)(b * Tk + (kt0) + rowk + 16) * D_ + h * DK_ + c4);  \
        int tkv = tid >> 4;                                                    \
        int bd = (tid & 15) >> 1;                                              \
        int id = (tid & 1) * 4;                                                \
        cpa16(sptr(&Vbt[s][((tkv >> 3) * 8 + bd) * 72 + (tkv & 7) * 8 + id]),  \
              Vg + (size_t)(b * Tk + (kt0) + tkv) * D_ + h * DK_ + c4);        \
        cpa16(sptr(&Vbt[s][(((tkv + 16) >> 3) * 8 + bd) * 72 + ((tkv + 16) & 7) * 8 + id]), \
              Vg + (size_t)(b * Tk + (kt0) + tkv + 16) * D_ + h * DK_ + c4);   \
        asm volatile("cp.async.commit_group;\n" ::: "memory");                 \
    } while (0)

    FKV(0, 0);   // prefetch chunk 0

    // load Q tile 128x64 (tf32-converted)
    {
        int row = tid >> 4, c4 = (tid & 15) * 4;
#pragma unroll
        for (int it = 0; it < 8; it++, row += 16) {
            float4 q4 = *(const float4*)(Q + (size_t)(b * T_ + tq0 + row) * D_ + h * DK_ + c4);
            q4.x = tf32r(q4.x); q4.y = tf32r(q4.y); q4.z = tf32r(q4.z); q4.w = tf32r(q4.w);
            *(float4*)&Qs[row * 68 + c4] = q4;
        }
    }

    int row0g = tq0 + w16 + r;
    int row1g = row0g + 8;
    bool rowok0 = causal ? (target[b * T_ + row0g] != 0) : true;
    bool rowok1 = causal ? (target[b * T_ + row1g] != 0) : true;

    float m0 = -1e30f, m1 = -1e30f, l0 = 0.f, l1 = 0.f;
    float o[8][4] = {};

    int nch = Tk >> 5;
    for (int ic = 0; ic < nch; ic++) {
        int s = ic & 1;
        if (ic + 1 < nch) {
            FKV(s ^ 1, (ic + 1) * 32);
            asm volatile("cp.async.wait_group 1;\n" ::: "memory");
        } else {
            asm volatile("cp.async.wait_group 0;\n" ::: "memory");
        }
        __syncthreads();   // stage s (and Qs on ic==0) visible to all warps
        const float* Ks = Kst[s];
        const float* Vb = Vbt[s];
        int kt0 = ic * 32;

        // S = Q K^T for this warp's 16 rows x 32 cols (4 nt blocks)
        float sc[4][4] = {};
#pragma unroll
        for (int kb = 0; kb < 64; kb += 8) {
            uint32_t aa[4];
            aa[0] = __float_as_uint(Qs[(w16 + r) * 68 + kb + c]);
            aa[1] = __float_as_uint(Qs[(w16 + 8 + r) * 68 + kb + c]);
            aa[2] = __float_as_uint(Qs[(w16 + r) * 68 + kb + 4 + c]);
            aa[3] = __float_as_uint(Qs[(w16 + 8 + r) * 68 + kb + 4 + c]);
#pragma unroll
            for (int nt = 0; nt < 4; nt++) {
                uint32_t bb[2];
                bb[0] = tf32u(Ks[(nt * 8 + r) * 68 + kb + c]);
                bb[1] = tf32u(Ks[(nt * 8 + r) * 68 + kb + 4 + c]);
                mma_tf32(sc[nt], aa, bb);
            }
        }

        // scale + mask + online softmax (rows row0g, row1g)
        float mx0 = -1e30f, mx1 = -1e30f;
#pragma unroll
        for (int nt = 0; nt < 4; nt++) {
            int col0 = kt0 + nt * 8 + 2 * c;
            int col1 = col0 + 1;
            bool ok00 = !causal || (rowok0 && col0 <= row0g);
            bool ok01 = !causal || (rowok0 && col1 <= row0g);
            bool ok10 = !causal || (rowok1 && col0 <= row1g);
            bool ok11 = !causal || (rowok1 && col1 <= row1g);
            sc[nt][0] = ok00 ? sc[nt][0] * 0.125f : -1e9f;
            sc[nt][1] = ok01 ? sc[nt][1] * 0.125f : -1e9f;
            sc[nt][2] = ok10 ? sc[nt][2] * 0.125f : -1e9f;
            sc[nt][3] = ok11 ? sc[nt][3] * 0.125f : -1e9f;
            mx0 = fmaxf(mx0, fmaxf(sc[nt][0], sc[nt][1]));
            mx1 = fmaxf(mx1, fmaxf(sc[nt][2], sc[nt][3]));
        }
        mx0 = fmaxf(mx0, __shfl_xor_sync(0xffffffffu, mx0, 1));
        mx0 = fmaxf(mx0, __shfl_xor_sync(0xffffffffu, mx0, 2));
        mx1 = fmaxf(mx1, __shfl_xor_sync(0xffffffffu, mx1, 1));
        mx1 = fmaxf(mx1, __shfl_xor_sync(0xffffffffu, mx1, 2));
        float mn0 = fmaxf(m0, mx0), mn1 = fmaxf(m1, mx1);
        float al0 = expf(m0 - mn0), al1 = expf(m1 - mn1);
        m0 = mn0; m1 = mn1;
        float rs0 = 0.f, rs1 = 0.f;
#pragma unroll
        for (int nt = 0; nt < 4; nt++) {
            sc[nt][0] = expf(sc[nt][0] - mn0);
            sc[nt][1] = expf(sc[nt][1] - mn0);
            sc[nt][2] = expf(sc[nt][2] - mn1);
            sc[nt][3] = expf(sc[nt][3] - mn1);
            rs0 += sc[nt][0] + sc[nt][1];
            rs1 += sc[nt][2] + sc[nt][3];
        }
        rs0 += __shfl_xor_sync(0xffffffffu, rs0, 1);
        rs0 += __shfl_xor_sync(0xffffffffu, rs0, 2);
        rs1 += __shfl_xor_sync(0xffffffffu, rs1, 1);
        rs1 += __shfl_xor_sync(0xffffffffu, rs1, 2);
        l0 = l0 * al0 + rs0;
        l1 = l1 * al1 + rs1;
#pragma unroll
        for (int nt = 0; nt < 8; nt++) {
            o[nt][0] *= al0; o[nt][1] *= al0;
            o[nt][2] *= al1; o[nt][3] *= al1;
        }

        // stage P (128x32) in smem, tf32-converted, stride 36
#pragma unroll
        for (int nt = 0; nt < 4; nt++) {
            *(float2*)&Ps[(w16 + r) * 36 + nt * 8 + 2 * c] =
                make_float2(tf32r(sc[nt][0]), tf32r(sc[nt][1]));
            *(float2*)&Ps[(w16 + 8 + r) * 36 + nt * 8 + 2 * c] =
                make_float2(tf32r(sc[nt][2]), tf32r(sc[nt][3]));
        }
        __syncwarp();

        // O += P V  (k = 32, 4 mma steps)
#pragma unroll
        for (int kbi = 0; kbi < 4; kbi++) {
            int kb = kbi * 8;
            uint32_t aa[4];
            aa[0] = __float_as_uint(Ps[(w16 + r) * 36 + kb + c]);
            aa[1] = __float_as_uint(Ps[(w16 + 8 + r) * 36 + kb + c]);
            aa[2] = __float_as_uint(Ps[(w16 + r) * 36 + kb + 4 + c]);
            aa[3] = __float_as_uint(Ps[(w16 + 8 + r) * 36 + kb + 4 + c]);
#pragma unroll
            for (int nt = 0; nt < 8; nt++) {
                uint32_t bb[2];
                bb[0] = tf32u(Vb[(kbi * 8 + nt) * 72 + c * 8 + r]);
                bb[1] = tf32u(Vb[(kbi * 8 + nt) * 72 + 32 + c * 8 + r]);
                mma_tf32(o[nt], aa, bb);
            }
        }
        __syncthreads();   // all warps done reading stage s before its reuse
    }

    float inv0 = 1.0f / l0, inv1 = 1.0f / l1;
#pragma unroll
    for (int nt = 0; nt < 8; nt++) {
        size_t g0 = (size_t)(b * T_ + row0g) * D_ + h * DK_ + nt * 8 + 2 * c;
        *(float2*)(O + g0)          = make_float2(o[nt][0] * inv0, o[nt][1] * inv0);
        *(float2*)(O + g0 + 8 * D_) = make_float2(o[nt][2] * inv1, o[nt][3] * inv1);
    }
}

// ---------------- host orchestration ----------------------------------------
extern "C" void kernel_launch(void* const* d_in, const int* in_sizes, int n_in,
                              void* d_out, int out_size)
{
    (void)in_sizes; (void)n_in; (void)out_size;
    float *x, *nb, *q, *k, *v, *a, *f, *mk, *mv;
    cudaGetSymbolAddress((void**)&x,  g_x);
    cudaGetSymbolAddress((void**)&nb, g_n);
    cudaGetSymbolAddress((void**)&q,  g_q);
    cudaGetSymbolAddress((void**)&k,  g_k);
    cudaGetSymbolAddress((void**)&v,  g_v);
    cudaGetSymbolAddress((void**)&a,  g_a);
    cudaGetSymbolAddress((void**)&f,  g_f);
    cudaGetSymbolAddress((void**)&mk, g_mk);
    cudaGetSymbolAddress((void**)&mv, g_mv);

    static int attr_set = 0;
    if (!attr_set) {
        cudaFuncSetAttribute(gemm_tc,  cudaFuncAttributeMaxDynamicSharedMemorySize, GEMM_SMEM);
        cudaFuncSetAttribute(flash_tc, cudaFuncAttributeMaxDynamicSharedMemorySize, FLASH_SMEM);
        attr_set = 1;
    }

    // setup_inputs() dict order (verified R2: rel_err 1.2e-6)
    const int*   target = (const int*)  d_in[0];
    const float* memory = (const float*)d_in[1];
    const float* emb    = (const float*)d_in[2];
    const float* ln_g   = (const float*)d_in[3];
    const float* ln_b   = (const float*)d_in[4];
    const float* ff_w1  = (const float*)d_in[5];
    const float* ff_b1  = (const float*)d_in[6];
    const float* ff_w2  = (const float*)d_in[7];
    const float* ff_b2  = (const float*)d_in[8];
    const float* sa_wq  = (const float*)d_in[9];
    const float* sa_bq  = (const float*)d_in[10];
    const float* ca_wq  = (const float*)d_in[11];
    const float* ca_bq  = (const float*)d_in[12];
    const float* sa_wk  = (const float*)d_in[13];
    const float* sa_bk  = (const float*)d_in[14];
    const float* ca_wk  = (const float*)d_in[15];
    const float* ca_bk  = (const float*)d_in[16];
    const float* sa_wv  = (const float*)d_in[17];
    const float* sa_bv  = (const float*)d_in[18];
    const float* ca_wv  = (const float*)d_in[19];
    const float* ca_bv  = (const float*)d_in[20];
    const float* sa_wo  = (const float*)d_in[21];
    const float* sa_bo  = (const float*)d_in[22];
    const float* ca_wo  = (const float*)d_in[23];
    const float* ca_bo  = (const float*)d_in[24];

    embed_kernel<<<(NTOK * D_ + 255) / 256, 256>>>(target, emb, x);

    // cross-attn K/V of memory: computed ONCE (shared weights, static memory)
    gemm_tc<<<dim3(D_ / 128, NMEM / 128), 256, GEMM_SMEM>>>(memory, ca_wk, ca_bk, nullptr, mk, NMEM, D_, D_, 0);
    gemm_tc<<<dim3(D_ / 128, NMEM / 128), 256, GEMM_SMEM>>>(memory, ca_wv, ca_bv, nullptr, mv, NMEM, D_, D_, 0);

    dim3 gProj(D_ / 128, NTOK / 128);   // (4,64)
    dim3 gFF1 (FF_ / 128, NTOK / 128);  // (16,64)
    dim3 gFlash(T_ / 128, B_ * H_);     // (2,256)

    for (int stk = 0; stk < 3; stk++) {
        // ---- self attention ----
        ln_kernel<<<NTOK / 8, 256>>>(x, nb, ln_g, ln_b, NTOK);
        gemm_tc<<<gProj, 256, GEMM_SMEM>>>(nb, sa_wq, sa_bq, nullptr, q, NTOK, D_, D_, 0);
        gemm_tc<<<gProj, 256, GEMM_SMEM>>>(nb, sa_wk, sa_bk, nullptr, k, NTOK, D_, D_, 0);
        gemm_tc<<<gProj, 256, GEMM_SMEM>>>(nb, sa_wv, sa_bv, nullptr, v, NTOK, D_, D_, 0);
        flash_tc<<<gFlash, 256, FLASH_SMEM>>>(q, k, v, a, T_, target, 1);
        gemm_tc<<<gProj, 256, GEMM_SMEM>>>(a, sa_wo, sa_bo, x, x, NTOK, D_, D_, 0);

        // ---- cross attention ----
        ln_kernel<<<NTOK / 8, 256>>>(x, nb, ln_g, ln_b, NTOK);
        gemm_tc<<<gProj, 256, GEMM_SMEM>>>(nb, ca_wq, ca_bq, nullptr, q, NTOK, D_, D_, 0);
        flash_tc<<<gFlash, 256, FLASH_SMEM>>>(q, mk, mv, a, TM_, nullptr, 0);
        gemm_tc<<<gProj, 256, GEMM_SMEM>>>(a, ca_wo, ca_bo, x, x, NTOK, D_, D_, 0);

        // ---- feed forward ----
        ln_kernel<<<NTOK / 8, 256>>>(x, nb, ln_g, ln_b, NTOK);
        gemm_tc<<<gFF1, 256, GEMM_SMEM>>>(nb, ff_w1, ff_b1, nullptr, f, NTOK, D_, FF_, 1);
        gemm_tc<<<gProj, 256, GEMM_SMEM>>>(f, ff_w2, ff_b2, x, x, NTOK, FF_, D_, 0);
    }

    ln_kernel<<<NTOK / 8, 256>>>(x, (float*)d_out, ln_g, ln_b, NTOK);
}

// round 16
// speedup vs baseline: 1.1608x; 1.0603x over previous
#include <cuda_runtime.h>
#include <math.h>
#include <stdint.h>

#define B_   32
#define T_   256
#define D_   512
#define H_   8
#define DK_  64
#define TM_  1024
#define FF_  2048
#define NTOK (B_*T_)      // 8192
#define NMEM (B_*TM_)     // 32768

// ---------------- scratch (static device globals; no allocation allowed) ----
__device__ float g_x [NTOK*D_];
__device__ float g_n [NTOK*D_];
__device__ float g_q [NTOK*D_];
__device__ float g_k [NTOK*D_];
__device__ float g_v [NTOK*D_];
__device__ float g_a [NTOK*D_];
__device__ float g_f [NTOK*FF_];
__device__ float g_mk[NMEM*D_];
__device__ float g_mv[NMEM*D_];

// ---------------- small helpers ---------------------------------------------
__device__ __forceinline__ float tf32r(float x) {
    uint32_t u;
    asm("cvt.rna.tf32.f32 %0, %1;" : "=r"(u) : "f"(x));
    return __uint_as_float(u);
}
__device__ __forceinline__ void mma_tf32(float* c, const uint32_t* a, const uint32_t* b) {
    asm volatile(
        "mma.sync.aligned.m16n8k8.row.col.f32.tf32.tf32.f32 "
        "{%0,%1,%2,%3}, {%4,%5,%6,%7}, {%8,%9}, {%0,%1,%2,%3};\n"
        : "+f"(c[0]), "+f"(c[1]), "+f"(c[2]), "+f"(c[3])
        : "r"(a[0]), "r"(a[1]), "r"(a[2]), "r"(a[3]), "r"(b[0]), "r"(b[1]));
}
__device__ __forceinline__ uint32_t sptr(const void* p) {
    return (uint32_t)__cvta_generic_to_shared(p);
}
__device__ __forceinline__ void cpa16(uint32_t dst, const void* src) {
    asm volatile("cp.async.cg.shared.global [%0], [%1], 16;\n"
                 :: "r"(dst), "l"(src) : "memory");
}

// ---------------- embedding + positional encoding ---------------------------
__global__ void embed_kernel(const int* __restrict__ target,
                             const float* __restrict__ emb,
                             float* __restrict__ x)
{
    int idx = blockIdx.x * blockDim.x + threadIdx.x;
    if (idx >= NTOK * D_) return;
    int n = idx / D_, d = idx - n * D_;
    int t = n % T_;
    int tok = target[n];
    float val = emb[(size_t)tok * D_ + d] * 22.62741699796952f;  // sqrt(512)
    int p2 = (d >> 1) << 1;
    float freq = expf((float)p2 * (-9.210340371976184f / 512.0f)); // -ln(10000)/D
    float ang = (float)t * freq;
    val += (d & 1) ? cosf(ang) : sinf(ang);
    x[idx] = val;
}

// ---------------- layernorm: one warp per 512-wide row ----------------------
__global__ void ln_kernel(const float* __restrict__ in, float* __restrict__ out,
                          const float* __restrict__ g, const float* __restrict__ b,
                          int nrows)
{
    int warp = threadIdx.x >> 5;
    int row  = blockIdx.x * 8 + warp;
    if (row >= nrows) return;
    int lane = threadIdx.x & 31;
    const float4* p = (const float4*)(in + (size_t)row * D_);
    float4 v[4];
    float sum = 0.f;
#pragma unroll
    for (int c = 0; c < 4; c++) {
        v[c] = p[lane + 32 * c];
        sum += v[c].x + v[c].y + v[c].z + v[c].w;
    }
#pragma unroll
    for (int o = 16; o > 0; o >>= 1) sum += __shfl_xor_sync(0xffffffffu, sum, o);
    float mu = sum * (1.0f / 512.0f);
    float vs = 0.f;
#pragma unroll
    for (int c = 0; c < 4; c++) {
        float dx = v[c].x - mu, dy = v[c].y - mu, dz = v[c].z - mu, dw = v[c].w - mu;
        vs += dx * dx + dy * dy + dz * dz + dw * dw;
    }
#pragma unroll
    for (int o = 16; o > 0; o >>= 1) vs += __shfl_xor_sync(0xffffffffu, vs, o);
    float rstd = rsqrtf(vs * (1.0f / 512.0f) + 1e-6f);
    float4* op = (float4*)(out + (size_t)row * D_);
    const float4* g4 = (const float4*)g;
    const float4* b4 = (const float4*)b;
#pragma unroll
    for (int c = 0; c < 4; c++) {
        float4 gg = g4[lane + 32 * c], bb = b4[lane + 32 * c], r;
        r.x = (v[c].x - mu) * rstd * gg.x + bb.x;
        r.y = (v[c].y - mu) * rstd * gg.y + bb.y;
        r.z = (v[c].z - mu) * rstd * gg.z + bb.z;
        r.w = (v[c].w - mu) * rstd * gg.w + bb.w;
        op[lane + 32 * c] = r;
    }
}

// ---------------- tf32 tensor-core GEMM, cp.async double-buffered -----------
// R12 winner with ONE change: fragment reads feed raw fp32 bits to mma.tf32
// (HW uses top 19 bits == RZ-truncated tf32) — removes 96 CVTs per K-tile.
#define GEMM_SMEM (2*(128*36 + 32*136)*4)
__global__ __launch_bounds__(256, 2) void gemm_tc(
    const float* __restrict__ A, const float* __restrict__ W,
    const float* __restrict__ bias, const float* __restrict__ resid,
    float* __restrict__ C, int M, int K, int N, int relu)
{
    extern __shared__ float gsm[];
    float* Asm[2] = {gsm, gsm + 128 * 36};
    float* Bsm[2] = {gsm + 2 * 128 * 36, gsm + 2 * 128 * 36 + 32 * 136};
    int tid = threadIdx.x;
    int lane = tid & 31, warp = tid >> 5;
    int wm = (warp >> 2) * 64;
    int wn = (warp & 3) * 32;
    size_t m0 = (size_t)blockIdx.y * 128, n0 = (size_t)blockIdx.x * 128;

    float acc[4][4][4] = {};

    int arow = tid >> 1, acq = (tid & 1) * 16;
    int brow = tid >> 3, bcq = (tid & 7) * 4;
    int r = lane >> 2, cg = lane & 3;

    const float* Abase = A + (m0 + arow) * K + acq;
    const float* Wbase = W + (size_t)brow * N + n0 + bcq;

#define GLOAD(s, k0)                                                           \
    do {                                                                       \
        _Pragma("unroll")                                                      \
        for (int j = 0; j < 4; j++)                                            \
            cpa16(sptr(&Asm[s][arow * 36 + acq + 4 * j]), Abase + (k0) + 4 * j); \
        _Pragma("unroll")                                                      \
        for (int j = 0; j < 4; j++)                                            \
            cpa16(sptr(&Bsm[s][brow * 136 + bcq + 32 * j]), Wbase + (size_t)(k0) * N + 32 * j); \
        asm volatile("cp.async.commit_group;\n" ::: "memory");                 \
    } while (0)

    GLOAD(0, 0);
    int st = 0;
    for (int k0 = 0; k0 < K; k0 += 32) {
        if (k0 + 32 < K) { GLOAD(st ^ 1, k0 + 32); asm volatile("cp.async.wait_group 1;\n" ::: "memory"); }
        else             { asm volatile("cp.async.wait_group 0;\n" ::: "memory"); }
        __syncthreads();
        const float* as = Asm[st];
        const float* bs = Bsm[st];
#pragma unroll
        for (int ks = 0; ks < 4; ks++) {
            int kb = ks * 8;
            uint32_t af[4][4], bf[4][2];
#pragma unroll
            for (int mi = 0; mi < 4; mi++) {
                int rb = wm + mi * 16;
                af[mi][0] = __float_as_uint(as[(rb + r) * 36 + kb + cg]);
                af[mi][1] = __float_as_uint(as[(rb + 8 + r) * 36 + kb + cg]);
                af[mi][2] = __float_as_uint(as[(rb + r) * 36 + kb + 4 + cg]);
                af[mi][3] = __float_as_uint(as[(rb + 8 + r) * 36 + kb + 4 + cg]);
            }
#pragma unroll
            for (int ni = 0; ni < 4; ni++) {
                bf[ni][0] = __float_as_uint(bs[(kb + cg) * 136 + wn + ni * 8 + r]);
                bf[ni][1] = __float_as_uint(bs[(kb + 4 + cg) * 136 + wn + ni * 8 + r]);
            }
#pragma unroll
            for (int mi = 0; mi < 4; mi++)
#pragma unroll
                for (int ni = 0; ni < 4; ni++)
                    mma_tf32(acc[mi][ni], af[mi], bf[ni]);
        }
        __syncthreads();
        st ^= 1;
    }

    int c2 = (lane & 3) * 2;
#pragma unroll
    for (int mi = 0; mi < 4; mi++) {
#pragma unroll
        for (int ni = 0; ni < 4; ni++) {
            size_t gm = m0 + wm + mi * 16 + r;
            size_t gn = n0 + wn + ni * 8 + c2;
            float b0v = bias[gn], b1v = bias[gn + 1];
            float v0 = acc[mi][ni][0] + b0v, v1 = acc[mi][ni][1] + b1v;
            float v2 = acc[mi][ni][2] + b0v, v3 = acc[mi][ni][3] + b1v;
            if (resid) {
                const float2 r0 = *(const float2*)(resid + gm * N + gn);
                const float2 r1 = *(const float2*)(resid + (gm + 8) * N + gn);
                v0 += r0.x; v1 += r0.y; v2 += r1.x; v3 += r1.y;
            }
            if (relu) {
                v0 = fmaxf(v0, 0.f); v1 = fmaxf(v1, 0.f);
                v2 = fmaxf(v2, 0.f); v3 = fmaxf(v3, 0.f);
            }
            *(float2*)(C + gm * N + gn) = make_float2(v0, v1);
            *(float2*)(C + (gm + 8) * N + gn) = make_float2(v2, v3);
        }
    }
}

// ---------------- tf32 tensor-core flash attention (R12 winner, verbatim) ----
#define FLASH_SMEM ((128*68 + 64*68 + 64*72 + 128*68) * 4)   // 105472 B
__global__ __launch_bounds__(256, 2) void flash_tc(
    const float* __restrict__ Q, const float* __restrict__ Kg,
    const float* __restrict__ Vg, float* __restrict__ O, int Tk,
    const int* __restrict__ target, int causal)
{
    extern __shared__ float fsm[];
    float* Qs = fsm;                          // [128][68]
    float* Ks = fsm + 128 * 68;               // [64][68]
    float* Vb = fsm + 128 * 68 + 64 * 68;     // [64 blocks][72]
    float* Ps = Vb + 64 * 72;                 // [128][68]

    int tid = threadIdx.x, lane = tid & 31, warp = tid >> 5;
    int z = blockIdx.y, b = z >> 3, h = z & 7;
    int tq0 = blockIdx.x * 128;
    int r = lane >> 2, c = lane & 3;
    int w16 = warp * 16;

    // load Q tile 128x64 (tf32-converted)
    {
        int row = tid >> 4, c4 = (tid & 15) * 4;
#pragma unroll
        for (int it = 0; it < 8; it++, row += 16) {
            float4 q4 = *(const float4*)(Q + (size_t)(b * T_ + tq0 + row) * D_ + h * DK_ + c4);
            q4.x = tf32r(q4.x); q4.y = tf32r(q4.y); q4.z = tf32r(q4.z); q4.w = tf32r(q4.w);
            *(float4*)&Qs[row * 68 + c4] = q4;
        }
    }

    int row0g = tq0 + w16 + r;
    int row1g = row0g + 8;
    bool rowok0 = causal ? (target[b * T_ + row0g] != 0) : true;
    bool rowok1 = causal ? (target[b * T_ + row1g] != 0) : true;

    float m0 = -1e30f, m1 = -1e30f, l0 = 0.f, l1 = 0.f;
    float o[8][4] = {};

    for (int kt0 = 0; kt0 < Tk; kt0 += 64) {
        // load K chunk -> Ks[tk][d]
        {
            int rowk = tid >> 4, c4 = (tid & 15) * 4;
#pragma unroll
            for (int it = 0; it < 4; it++, rowk += 16) {
                float4 k4 = *(const float4*)(Kg + (size_t)(b * Tk + kt0 + rowk) * D_ + h * DK_ + c4);
                k4.x = tf32r(k4.x); k4.y = tf32r(k4.y); k4.z = tf32r(k4.z); k4.w = tf32r(k4.w);
                *(float4*)&Ks[rowk * 68 + c4] = k4;
            }
        }
        // load V chunk transposed into block layout
        {
            int d = tid & 63, tk = tid >> 6;
#pragma unroll
            for (int it = 0; it < 16; it++, tk += 4) {
                float v = Vg[(size_t)(b * Tk + kt0 + tk) * D_ + h * DK_ + d];
                Vb[((tk >> 3) * 8 + (d >> 3)) * 72 + (tk & 7) * 8 + (d & 7)] = tf32r(v);
            }
        }
        __syncthreads();

        // S = Q K^T for this warp's 16 rows x 64 cols
        float sc[8][4] = {};
#pragma unroll
        for (int kb = 0; kb < 64; kb += 8) {
            uint32_t aa[4];
            aa[0] = __float_as_uint(Qs[(w16 + r) * 68 + kb + c]);
            aa[1] = __float_as_uint(Qs[(w16 + 8 + r) * 68 + kb + c]);
            aa[2] = __float_as_uint(Qs[(w16 + r) * 68 + kb + 4 + c]);
            aa[3] = __float_as_uint(Qs[(w16 + 8 + r) * 68 + kb + 4 + c]);
#pragma unroll
            for (int nt = 0; nt < 8; nt++) {
                uint32_t bb[2];
                bb[0] = __float_as_uint(Ks[(nt * 8 + r) * 68 + kb + c]);
                bb[1] = __float_as_uint(Ks[(nt * 8 + r) * 68 + kb + 4 + c]);
                mma_tf32(sc[nt], aa, bb);
            }
        }

        // scale + mask + online softmax (rows row0g, row1g)
        float mx0 = -1e30f, mx1 = -1e30f;
#pragma unroll
        for (int nt = 0; nt < 8; nt++) {
            int col0 = kt0 + nt * 8 + 2 * c;
            int col1 = col0 + 1;
            bool ok00 = !causal || (rowok0 && col0 <= row0g);
            bool ok01 = !causal || (rowok0 && col1 <= row0g);
            bool ok10 = !causal || (rowok1 && col0 <= row1g);
            bool ok11 = !causal || (rowok1 && col1 <= row1g);
            sc[nt][0] = ok00 ? sc[nt][0] * 0.125f : -1e9f;
            sc[nt][1] = ok01 ? sc[nt][1] * 0.125f : -1e9f;
            sc[nt][2] = ok10 ? sc[nt][2] * 0.125f : -1e9f;
            sc[nt][3] = ok11 ? sc[nt][3] * 0.125f : -1e9f;
            mx0 = fmaxf(mx0, fmaxf(sc[nt][0], sc[nt][1]));
            mx1 = fmaxf(mx1, fmaxf(sc[nt][2], sc[nt][3]));
        }
        mx0 = fmaxf(mx0, __shfl_xor_sync(0xffffffffu, mx0, 1));
        mx0 = fmaxf(mx0, __shfl_xor_sync(0xffffffffu, mx0, 2));
        mx1 = fmaxf(mx1, __shfl_xor_sync(0xffffffffu, mx1, 1));
        mx1 = fmaxf(mx1, __shfl_xor_sync(0xffffffffu, mx1, 2));
        float mn0 = fmaxf(m0, mx0), mn1 = fmaxf(m1, mx1);
        float al0 = expf(m0 - mn0), al1 = expf(m1 - mn1);
        m0 = mn0; m1 = mn1;
        float rs0 = 0.f, rs1 = 0.f;
#pragma unroll
        for (int nt = 0; nt < 8; nt++) {
            sc[nt][0] = expf(sc[nt][0] - mn0);
            sc[nt][1] = expf(sc[nt][1] - mn0);
            sc[nt][2] = expf(sc[nt][2] - mn1);
            sc[nt][3] = expf(sc[nt][3] - mn1);
            rs0 += sc[nt][0] + sc[nt][1];
            rs1 += sc[nt][2] + sc[nt][3];
        }
        rs0 += __shfl_xor_sync(0xffffffffu, rs0, 1);
        rs0 += __shfl_xor_sync(0xffffffffu, rs0, 2);
        rs1 += __shfl_xor_sync(0xffffffffu, rs1, 1);
        rs1 += __shfl_xor_sync(0xffffffffu, rs1, 2);
        l0 = l0 * al0 + rs0;
        l1 = l1 * al1 + rs1;
#pragma unroll
        for (int nt = 0; nt < 8; nt++) {
            o[nt][0] *= al0; o[nt][1] *= al0;
            o[nt][2] *= al1; o[nt][3] *= al1;
        }

        // stage P in smem (warp-private rows), tf32-converted
#pragma unroll
        for (int nt = 0; nt < 8; nt++) {
            *(float2*)&Ps[(w16 + r) * 68 + nt * 8 + 2 * c] =
                make_float2(tf32r(sc[nt][0]), tf32r(sc[nt][1]));
            *(float2*)&Ps[(w16 + 8 + r) * 68 + nt * 8 + 2 * c] =
                make_float2(tf32r(sc[nt][2]), tf32r(sc[nt][3]));
        }
        __syncwarp();

        // O += P V
#pragma unroll
        for (int kb = 0; kb < 64; kb += 8) {
            uint32_t aa[4];
            aa[0] = __float_as_uint(Ps[(w16 + r) * 68 + kb + c]);
            aa[1] = __float_as_uint(Ps[(w16 + 8 + r) * 68 + kb + c]);
            aa[2] = __float_as_uint(Ps[(w16 + r) * 68 + kb + 4 + c]);
            aa[3] = __float_as_uint(Ps[(w16 + 8 + r) * 68 + kb + 4 + c]);
            int kbi = kb >> 3;
#pragma unroll
            for (int nt = 0; nt < 8; nt++) {
                uint32_t bb[2];
                bb[0] = __float_as_uint(Vb[(kbi * 8 + nt) * 72 + c * 8 + r]);
                bb[1] = __float_as_uint(Vb[(kbi * 8 + nt) * 72 + 32 + c * 8 + r]);
                mma_tf32(o[nt], aa, bb);
            }
        }
        __syncthreads();
    }

    float inv0 = 1.0f / l0, inv1 = 1.0f / l1;
#pragma unroll
    for (int nt = 0; nt < 8; nt++) {
        size_t g0 = (size_t)(b * T_ + row0g) * D_ + h * DK_ + nt * 8 + 2 * c;
        *(float2*)(O + g0)          = make_float2(o[nt][0] * inv0, o[nt][1] * inv0);
        *(float2*)(O + g0 + 8 * D_) = make_float2(o[nt][2] * inv1, o[nt][3] * inv1);
    }
}

// ---------------- host orchestration ----------------------------------------
extern "C" void kernel_launch(void* const* d_in, const int* in_sizes, int n_in,
                              void* d_out, int out_size)
{
    (void)in_sizes; (void)n_in; (void)out_size;
    float *x, *nb, *q, *k, *v, *a, *f, *mk, *mv;
    cudaGetSymbolAddress((void**)&x,  g_x);
    cudaGetSymbolAddress((void**)&nb, g_n);
    cudaGetSymbolAddress((void**)&q,  g_q);
    cudaGetSymbolAddress((void**)&k,  g_k);
    cudaGetSymbolAddress((void**)&v,  g_v);
    cudaGetSymbolAddress((void**)&a,  g_a);
    cudaGetSymbolAddress((void**)&f,  g_f);
    cudaGetSymbolAddress((void**)&mk, g_mk);
    cudaGetSymbolAddress((void**)&mv, g_mv);

    static int attr_set = 0;
    if (!attr_set) {
        cudaFuncSetAttribute(gemm_tc,  cudaFuncAttributeMaxDynamicSharedMemorySize, GEMM_SMEM);
        cudaFuncSetAttribute(flash_tc, cudaFuncAttributeMaxDynamicSharedMemorySize, FLASH_SMEM);
        attr_set = 1;
    }

    // setup_inputs() dict order (verified R2: rel_err 1.2e-6)
    const int*   target = (const int*)  d_in[0];
    const float* memory = (const float*)d_in[1];
    const float* emb    = (const float*)d_in[2];
    const float* ln_g   = (const float*)d_in[3];
    const float* ln_b   = (const float*)d_in[4];
    const float* ff_w1  = (const float*)d_in[5];
    const float* ff_b1  = (const float*)d_in[6];
    const float* ff_w2  = (const float*)d_in[7];
    const float* ff_b2  = (const float*)d_in[8];
    const float* sa_wq  = (const float*)d_in[9];
    const float* sa_bq  = (const float*)d_in[10];
    const float* ca_wq  = (const float*)d_in[11];
    const float* ca_bq  = (const float*)d_in[12];
    const float* sa_wk  = (const float*)d_in[13];
    const float* sa_bk  = (const float*)d_in[14];
    const float* ca_wk  = (const float*)d_in[15];
    const float* ca_bk  = (const float*)d_in[16];
    const float* sa_wv  = (const float*)d_in[17];
    const float* sa_bv  = (const float*)d_in[18];
    const float* ca_wv  = (const float*)d_in[19];
    const float* ca_bv  = (const float*)d_in[20];
    const float* sa_wo  = (const float*)d_in[21];
    const float* sa_bo  = (const float*)d_in[22];
    const float* ca_wo  = (const float*)d_in[23];
    const float* ca_bo  = (const float*)d_in[24];

    embed_kernel<<<(NTOK * D_ + 255) / 256, 256>>>(target, emb, x);

    // cross-attn K/V of memory: computed ONCE (shared weights, static memory)
    gemm_tc<<<dim3(D_ / 128, NMEM / 128), 256, GEMM_SMEM>>>(memory, ca_wk, ca_bk, nullptr, mk, NMEM, D_, D_, 0);
    gemm_tc<<<dim3(D_ / 128, NMEM / 128), 256, GEMM_SMEM>>>(memory, ca_wv, ca_bv, nullptr, mv, NMEM, D_, D_, 0);

    dim3 gProj(D_ / 128, NTOK / 128);   // (4,64)
    dim3 gFF1 (FF_ / 128, NTOK / 128);  // (16,64)
    dim3 gFlash(T_ / 128, B_ * H_);     // (2,256)

    for (int stk = 0; stk < 3; stk++) {
        // ---- self attention ----
        ln_kernel<<<NTOK / 8, 256>>>(x, nb, ln_g, ln_b, NTOK);
        gemm_tc<<<gProj, 256, GEMM_SMEM>>>(nb, sa_wq, sa_bq, nullptr, q, NTOK, D_, D_, 0);
        gemm_tc<<<gProj, 256, GEMM_SMEM>>>(nb, sa_wk, sa_bk, nullptr, k, NTOK, D_, D_, 0);
        gemm_tc<<<gProj, 256, GEMM_SMEM>>>(nb, sa_wv, sa_bv, nullptr, v, NTOK, D_, D_, 0);
        flash_tc<<<gFlash, 256, FLASH_SMEM>>>(q, k, v, a, T_, target, 1);
        gemm_tc<<<gProj, 256, GEMM_SMEM>>>(a, sa_wo, sa_bo, x, x, NTOK, D_, D_, 0);

        // ---- cross attention ----
        ln_kernel<<<NTOK / 8, 256>>>(x, nb, ln_g, ln_b, NTOK);
        gemm_tc<<<gProj, 256, GEMM_SMEM>>>(nb, ca_wq, ca_bq, nullptr, q, NTOK, D_, D_, 0);
        flash_tc<<<gFlash, 256, FLASH_SMEM>>>(q, mk, mv, a, TM_, nullptr, 0);
        gemm_tc<<<gProj, 256, GEMM_SMEM>>>(a, ca_wo, ca_bo, x, x, NTOK, D_, D_, 0);

        // ---- feed forward ----
        ln_kernel<<<NTOK / 8, 256>>>(x, nb, ln_g, ln_b, NTOK);
        gemm_tc<<<gFF1, 256, GEMM_SMEM>>>(nb, ff_w1, ff_b1, nullptr, f, NTOK, D_, FF_, 1);
        gemm_tc<<<gProj, 256, GEMM_SMEM>>>(f, ff_w2, ff_b2, x, x, NTOK, FF_, D_, 0);
    }

    ln_kernel<<<NTOK / 8, 256>>>(x, (float*)d_out, ln_g, ln_b, NTOK);
}